// round 16
// baseline (speedup 1.0000x reference)
#include <cuda_runtime.h>
#include <cuda_bf16.h>

// Problem constants: b=1, h=w=64, s=5, H=W=1024, ps=32, q=8
#define GRID_T   64
#define NSTROKE  5
#define IMG      1024
#define PLANE    (IMG * IMG)            // 1048576

__device__ __forceinline__ float tanh_(float x) {
    float r; asm("tanh.approx.f32 %0,%1;" : "=f"(r) : "f"(x)); return r;
}

// ---------------------------------------------------------------------------
// Single fused kernel. Block = 2x2 padded 16x16 cells (32x32 px), 256 threads,
// 4 px/thread (rows ty+{0,4,8,12}).
//
// Stroke constants folded to the TILE origin (global pixel coords):
//     u = Gx*C + Gy*S + U0'' ;  v = Gy*C - Gx*S + V0''
// so ONE staging pass (threads 0..44, one per (tile,stroke)) covers the 3x3
// tiles used by all 4 cells.
//
// Inner loop alpha factorization (colors pre-scaled by 0.25 at staging):
//     s  = (1+t1)(1+t2) = fma(f1, t2, f1),  f1 = 1+t1
//     sT = s*T ;  acc += sT * (0.25c) ;  T = fma(sT, -0.25, T)
// 9 fma-pipe ops per pixel-stroke (was 10).
//
// Front-to-back blend (pass p=3..0, strokes i=cnt-1..0); canvas read after
// the loop: out = acc + canvas*T.
// ---------------------------------------------------------------------------
__global__ void __launch_bounds__(256, 6)
render_kernel(const float* __restrict__ param,
              const int*   __restrict__ decision,
              const float* __restrict__ canvas,
              float*       __restrict__ out) {
    __shared__ float4 sA[9][NSTROKE];    // (C, S, U0'', V0'')  [scaled by 25]
    __shared__ float4 sB[9][NSTROKE];    // (W, H, -, -)        [scaled by 25]
    __shared__ float4 sC[9][NSTROKE];    // (0.25*cr, 0.25*cg, 0.25*cb, -)
    __shared__ int    sCnt[9];

    const int r0 = 2 * blockIdx.y - 1;   // tile row of local tile (0,*)
    const int c0 = 2 * blockIdx.x - 1;   // tile col of local tile (*,0)
    const int tid = threadIdx.x;

    // --- staging: one thread per (tile, stroke), tiles = 3x3 around block ---
    if (tid < 9 * NSTROKE) {
        const int lt = tid / NSTROKE;    // local tile 0..8
        const int i  = tid - lt * NSTROKE;
        const int r  = r0 + lt / 3;
        const int c  = c0 + lt % 3;
        const bool valid = ((unsigned)r < 64u) && ((unsigned)c < 64u);
        const int t = r * GRID_T + c;

        int dec[NSTROKE];
        #pragma unroll
        for (int j = 0; j < NSTROKE; j++)
            dec[j] = valid ? decision[t * NSTROKE + j] : 0;

        int cnt = 0;
        #pragma unroll
        for (int j = 0; j < NSTROKE; j++) cnt += (dec[j] != 0);
        if (i == 0) sCnt[lt] = cnt;

        if (dec[i] != 0) {
            int pos = 0;
            #pragma unroll
            for (int j = 0; j < NSTROKE; j++) pos += (j < i) && (dec[j] != 0);

            const float* q = param + (size_t)(t * NSTROKE + i) * 12;
            float p8[8];
            #pragma unroll
            for (int k = 0; k < 8; k++)
                p8[k] = __fdividef(1.0f, 1.0f + __expf(-q[k]));  // sigmoid

            float x0 = p8[0], yc = p8[1];
            float W = 12.5f * fmaxf(p8[2], 0.01f);   // 25 * (wd/2)
            float H = 12.5f * fmaxf(p8[3], 0.01f);
            float th = p8[4] * 3.14159265358979323846f;
            float st, ct;
            __sincosf(th, &st, &ct);

            float C  = 25.0f * ct, S = 25.0f * st;
            float U0 = -(x0 * C + yc * S);
            float V0 =  (x0 * S - yc * C);

            // fold TILE origin (16r,16c padded px = 0.5r,0.5c tile units)
            float fc = 0.5f * (float)c, fr = 0.5f * (float)r;
            float U0p = U0 - (fc * C + fr * S);
            float V0p = V0 + (fc * S - fr * C);

            sA[lt][pos] = make_float4(C, S, U0p, V0p);
            sB[lt][pos] = make_float4(W, H, 0.125f * S, 0.125f * C);
            sC[lt][pos] = make_float4(0.25f * p8[5], 0.25f * p8[6],
                                      0.25f * p8[7], 0.f);
        }
    }
    __syncthreads();

    // --- render: cell = tid>>6 (warp-uniform); 4 px/thread ---
    const int cl = tid >> 6;             // 0..3
    const int t6 = tid & 63;
    const int tx = t6 & 15;
    const int ty = t6 >> 4;              // 0..3
    const int a  = 2 * blockIdx.y + (cl >> 1);   // padded cell row
    const int bb = 2 * blockIdx.x + (cl & 1);    // padded cell col

    const int Xp  = 16 * bb + tx;        // padded pixel coords
    const int Yp0 = 16 * a + ty;
    const float Gx = ((float)Xp  + 0.5f) * 0.03125f;   // global tile units
    const float Gy = ((float)Yp0 + 0.5f) * 0.03125f;

    float aR[4] = {0.f, 0.f, 0.f, 0.f};
    float aG[4] = {0.f, 0.f, 0.f, 0.f};
    float aB[4] = {0.f, 0.f, 0.f, 0.f};
    float T[4]  = {1.f, 1.f, 1.f, 1.f};

    const int PR[4] = {0, 1, 1, 0};
    const int PC[4] = {0, 1, 0, 1};

    #pragma unroll
    for (int p = 3; p >= 0; --p) {       // reversed passes => front-to-back
        int r = (((a - 1) & 1) == PR[p]) ? (a - 1) : a;
        int c = (((bb - 1) & 1) == PC[p]) ? (bb - 1) : bb;
        int lt = (r - r0) * 3 + (c - c0);
        int cn = sCnt[lt];

        for (int i = cn - 1; i >= 0; --i) {      // reversed strokes
            float4 A  = sA[lt][i];
            float4 B  = sB[lt][i];
            float4 Cc = sC[lt][i];

            float u = fmaf(Gx, A.x, fmaf(Gy, A.y, A.z));
            float v = fmaf(Gy, A.x, fmaf(-Gx, A.y, A.w));

            #pragma unroll
            for (int k = 0; k < 4; k++) {
                float t1 = tanh_(B.x - fabsf(u));
                float t2 = tanh_(B.y - fabsf(v));
                float f1 = 1.0f + t1;
                float s  = fmaf(f1, t2, f1);     // (1+t1)(1+t2)
                float sT = s * T[k];
                aR[k] = fmaf(sT, Cc.x, aR[k]);   // colors carry the 0.25
                aG[k] = fmaf(sT, Cc.y, aG[k]);
                aB[k] = fmaf(sT, Cc.z, aB[k]);
                T[k]  = fmaf(sT, -0.25f, T[k]);
                u += B.z;                        // +4 rows: du = 0.125*S
                v += B.w;                        //          dv = 0.125*C
            }
        }
    }

    // --- late canvas read + composite ---
    const int x  = Xp - 8;               // q = 8
    const int y0 = Yp0 - 8;
    const bool vx = (unsigned)x < (unsigned)IMG;
    #pragma unroll
    for (int k = 0; k < 4; k++) {
        int y = y0 + 4 * k;
        if (vx && ((unsigned)y < (unsigned)IMG)) {
            int idx = y * IMG + x;
            out[idx]             = fmaf(canvas[idx],             T[k], aR[k]);
            out[PLANE + idx]     = fmaf(canvas[PLANE + idx],     T[k], aG[k]);
            out[2 * PLANE + idx] = fmaf(canvas[2 * PLANE + idx], T[k], aB[k]);
        }
    }
}

// ---------------------------------------------------------------------------
extern "C" void kernel_launch(void* const* d_in, const int* in_sizes, int n_in,
                              void* d_out, int out_size) {
    const float* param    = (const float*)d_in[0];   // (1,64,64,5,12) f32
    const int*   decision = (const int*)  d_in[1];   // (1,64,64,5)    i32
    const float* canvas   = (const float*)d_in[2];   // (1,3,1024,1024) f32
    float*       out      = (float*)d_out;           // (1,3,1024,1024) f32

    dim3 bs(256);            // 2x2 cells per block, 4 px/thread
    dim3 gs(33, 33);         // 66x66 cells (index 65 auto-invalid)
    render_kernel<<<gs, bs>>>(param, decision, canvas, out);
}